// round 5
// baseline (speedup 1.0000x reference)
#include <cuda_runtime.h>
#include <cuda_bf16.h>
#include <cstdint>
#include <math.h>

#define T_TOK 8192
#define HDIM 1024
#define FDIM 4096
#define NEXP 8
#define NSLOT (2*T_TOK)

#define BM 128
#define BN 128
#define BK 16
#define SA_STRIDE 20
#define SB_STRIDE 136

// ---------------- scratch (device globals; no allocation allowed) ----------------
__device__ float g_xc [(size_t)T_TOK * HDIM];          // tf32-rounded x
__device__ float g_w1c[(size_t)NEXP * HDIM * FDIM];    // tf32-rounded w1
__device__ float g_w2c[(size_t)NEXP * FDIM * HDIM];    // tf32-rounded w2
__device__ float g_hid[(size_t)NSLOT * FDIM];          // gelu intermediate (tf32-rounded)
__device__ float g_wTE[T_TOK * NEXP];                  // dense routing weights
__device__ int   g_topk[T_TOK * 2];                    // top-2 expert ids per token
__device__ int   g_tokList[NEXP * T_TOK];              // per-expert token lists (ascending)
__device__ int   g_counts[NEXP];
__device__ int   g_bases[NEXP];

// ---------------- helpers ----------------
__device__ __forceinline__ float to_tf32(float x) {
    uint32_t u;
    asm("cvt.rna.tf32.f32 %0, %1;" : "=r"(u) : "f"(x));
    return __uint_as_float(u);
}
__device__ __forceinline__ void cp16(uint32_t s, const void* g) {
    asm volatile("cp.async.cg.shared.global [%0], [%1], 16;\n" :: "r"(s), "l"(g));
}
__device__ __forceinline__ void cp_commit() { asm volatile("cp.async.commit_group;\n" ::: "memory"); }
__device__ __forceinline__ void cp_wait0()  { asm volatile("cp.async.wait_group 0;\n" ::: "memory"); }

__device__ __forceinline__ void mma_tf32(float* d, const uint32_t* a, const uint32_t* b) {
    asm volatile(
        "mma.sync.aligned.m16n8k8.row.col.f32.tf32.tf32.f32 "
        "{%0,%1,%2,%3}, {%4,%5,%6,%7}, {%8,%9}, {%0,%1,%2,%3};\n"
        : "+f"(d[0]), "+f"(d[1]), "+f"(d[2]), "+f"(d[3])
        : "r"(a[0]), "r"(a[1]), "r"(a[2]), "r"(a[3]), "r"(b[0]), "r"(b[1]));
}

// ---------------- small kernels ----------------
__global__ void zero_kernel(float4* out, int n4) {
    int i = blockIdx.x * blockDim.x + threadIdx.x;
    int st = gridDim.x * blockDim.x;
    float4 z = make_float4(0.f, 0.f, 0.f, 0.f);
    for (; i < n4; i += st) out[i] = z;
}

__device__ __forceinline__ void cvt_body(const float* __restrict__ src, float* __restrict__ dst, int n4) {
    int i = blockIdx.x * blockDim.x + threadIdx.x;
    int st = gridDim.x * blockDim.x;
    const float4* s4 = (const float4*)src;
    float4* d4 = (float4*)dst;
    for (; i < n4; i += st) {
        float4 v = s4[i];
        v.x = to_tf32(v.x); v.y = to_tf32(v.y);
        v.z = to_tf32(v.z); v.w = to_tf32(v.w);
        d4[i] = v;
    }
}
__global__ void cvt_x_kernel (const float* src) { cvt_body(src, g_xc,  T_TOK * HDIM / 4); }
__global__ void cvt_w1_kernel(const float* src) { cvt_body(src, g_w1c, NEXP * HDIM * FDIM / 4); }
__global__ void cvt_w2_kernel(const float* src) { cvt_body(src, g_w2c, NEXP * FDIM * HDIM / 4); }

// Router: warp per token. fp32 logits -> softmax -> stable top-2.
__global__ void router_kernel(const float* __restrict__ x, const float* __restrict__ rw) {
    __shared__ float sw[NEXP * HDIM];   // 32KB
    for (int i = threadIdx.x; i < NEXP * HDIM; i += blockDim.x) sw[i] = rw[i];
    __syncthreads();
    int warp = threadIdx.x >> 5, lane = threadIdx.x & 31;
    int t = blockIdx.x * 8 + warp;
    const float* xr = x + (size_t)t * HDIM;
    float acc[NEXP];
#pragma unroll
    for (int e = 0; e < NEXP; e++) acc[e] = 0.f;
    for (int i = lane; i < HDIM; i += 32) {
        float xv = xr[i];
#pragma unroll
        for (int e = 0; e < NEXP; e++) acc[e] += xv * sw[e * HDIM + i];
    }
#pragma unroll
    for (int off = 16; off > 0; off >>= 1)
#pragma unroll
        for (int e = 0; e < NEXP; e++) acc[e] += __shfl_down_sync(0xffffffffu, acc[e], off);
    if (lane == 0) {
        float mx = acc[0];
#pragma unroll
        for (int e = 1; e < NEXP; e++) mx = fmaxf(mx, acc[e]);
        float p[NEXP]; float s = 0.f;
#pragma unroll
        for (int e = 0; e < NEXP; e++) { p[e] = expf(acc[e] - mx); s += p[e]; }
        int i0 = 0;
#pragma unroll
        for (int e = 1; e < NEXP; e++) if (p[e] > p[i0]) i0 = e;
        int i1 = (i0 == 0) ? 1 : 0;
#pragma unroll
        for (int e = 0; e < NEXP; e++) if (e != i0 && p[e] > p[i1]) i1 = e;
        float inv = 1.f / s;
#pragma unroll
        for (int e = 0; e < NEXP; e++)
            g_wTE[t * NEXP + e] = (e == i0 || e == i1) ? p[e] * inv : 0.f;
        g_topk[t * 2]     = i0;
        g_topk[t * 2 + 1] = i1;
    }
}

// Deterministic compaction: one block per expert, ascending token order.
__global__ void compact_kernel() {
    int e = blockIdx.x;
    __shared__ int wsum[8];
    __shared__ int sBase;
    int tid = threadIdx.x, wid = tid >> 5, lane = tid & 31;
    if (tid == 0) sBase = 0;
    __syncthreads();
    for (int t0 = 0; t0 < T_TOK; t0 += 256) {
        int t = t0 + tid;
        bool sel = (g_topk[t * 2] == e) || (g_topk[t * 2 + 1] == e);
        unsigned bal = __ballot_sync(0xffffffffu, sel);
        int lanePre = __popc(bal & ((1u << lane) - 1u));
        if (lane == 0) wsum[wid] = __popc(bal);
        __syncthreads();
        int wpre = 0;
        for (int w = 0; w < wid; w++) wpre += wsum[w];
        if (sel) g_tokList[e * T_TOK + sBase + wpre + lanePre] = t;
        __syncthreads();
        if (tid == 0) {
            int tt = 0;
            for (int w = 0; w < 8; w++) tt += wsum[w];
            sBase += tt;
        }
        __syncthreads();
    }
    if (tid == 0) g_counts[e] = sBase;
}

__global__ void bases_kernel() {
    if (threadIdx.x == 0 && blockIdx.x == 0) {
        int s = 0;
        for (int e = 0; e < NEXP; e++) { g_bases[e] = s; s += g_counts[e]; }
    }
}

// ---------------- GEMM1: hid = gelu(X[gather] @ W1_e + b1_e) ----------------
__global__ __launch_bounds__(256) void gemm1_kernel(const float* __restrict__ b1) {
    const int e = blockIdx.z;
    const int count = g_counts[e];
    const int mt = blockIdx.y;
    if (mt * BM >= count) return;
    const int nBase = blockIdx.x * BN;
    const int base = g_bases[e];

    __shared__ float sA[2][BM * SA_STRIDE];
    __shared__ float sB[2][BK * SB_STRIDE];
    __shared__ int sTok[BM];

    const int tid = threadIdx.x;
    if (tid < BM) {
        int m = mt * BM + tid;
        if (m >= count) m = count - 1;
        sTok[tid] = g_tokList[e * T_TOK + m];
    }
    __syncthreads();

    // A: 128x16 tile, 512 16B chunks, 2 per thread (same row)
    const int chA = tid * 2;
    const int rA = chA >> 2;
    const int ccA = chA & 3;
    const float* gA = g_xc + (size_t)sTok[rA] * HDIM + ccA * 4;
    uint32_t sAaddr0 = (uint32_t)__cvta_generic_to_shared(&sA[0][rA * SA_STRIDE + ccA * 4]);
    uint32_t sAaddr1 = (uint32_t)__cvta_generic_to_shared(&sA[1][rA * SA_STRIDE + ccA * 4]);

    // B: 16x128 tile
    const int chB = tid * 2;
    const int rB = chB >> 5;
    const int ccB = chB & 31;
    const float* gB = g_w1c + ((size_t)e * HDIM + rB) * FDIM + nBase + ccB * 4;
    uint32_t sBaddr0 = (uint32_t)__cvta_generic_to_shared(&sB[0][rB * SB_STRIDE + ccB * 4]);
    uint32_t sBaddr1 = (uint32_t)__cvta_generic_to_shared(&sB[1][rB * SB_STRIDE + ccB * 4]);

    auto loadTile = [&](int stage, int kt) {
        const float* a0 = gA + kt * BK;
        uint32_t sa = stage ? sAaddr1 : sAaddr0;
        cp16(sa, a0);
        cp16(sa + 16, a0 + 4);
        const float* b0 = gB + (size_t)kt * BK * FDIM;
        uint32_t sb = stage ? sBaddr1 : sBaddr0;
        cp16(sb, b0);
        cp16(sb + 16, b0 + 4);
    };

    float acc[4][4][4];
#pragma unroll
    for (int a = 0; a < 4; a++)
#pragma unroll
        for (int b = 0; b < 4; b++)
#pragma unroll
            for (int c = 0; c < 4; c++) acc[a][b][c] = 0.f;

    const int warp = tid >> 5, lane = tid & 31;
    const int wr = warp >> 2, wc = warp & 3;
    const int gq = lane >> 2, c4 = lane & 3;

    const int KT = HDIM / BK;
    loadTile(0, 0);
    cp_commit();
    for (int kt = 0; kt < KT; kt++) {
        cp_wait0();
        __syncthreads();
        if (kt + 1 < KT) { loadTile((kt + 1) & 1, kt + 1); cp_commit(); }
        const float* pA = sA[kt & 1];
        const float* pB = sB[kt & 1];
#pragma unroll
        for (int ks = 0; ks < 2; ks++) {
            const int k0 = ks * 8;
            uint32_t af[4][4], bf[4][2];
#pragma unroll
            for (int mi = 0; mi < 4; mi++) {
                int r0 = wr * 64 + mi * 16 + gq;
                af[mi][0] = __float_as_uint(pA[r0 * SA_STRIDE + k0 + c4]);
                af[mi][1] = __float_as_uint(pA[(r0 + 8) * SA_STRIDE + k0 + c4]);
                af[mi][2] = __float_as_uint(pA[r0 * SA_STRIDE + k0 + c4 + 4]);
                af[mi][3] = __float_as_uint(pA[(r0 + 8) * SA_STRIDE + k0 + c4 + 4]);
            }
#pragma unroll
            for (int ni = 0; ni < 4; ni++) {
                int cb = wc * 32 + ni * 8 + gq;
                bf[ni][0] = __float_as_uint(pB[(k0 + c4) * SB_STRIDE + cb]);
                bf[ni][1] = __float_as_uint(pB[(k0 + c4 + 4) * SB_STRIDE + cb]);
            }
#pragma unroll
            for (int mi = 0; mi < 4; mi++)
#pragma unroll
                for (int ni = 0; ni < 4; ni++)
                    mma_tf32(acc[mi][ni], af[mi], bf[ni]);
        }
        __syncthreads();
    }

    // epilogue: bias + exact gelu + tf32 round + store
#pragma unroll
    for (int ni = 0; ni < 4; ni++) {
        int col = nBase + wc * 32 + ni * 8 + 2 * c4;
        float bb0 = b1[e * FDIM + col];
        float bb1 = b1[e * FDIM + col + 1];
#pragma unroll
        for (int mi = 0; mi < 4; mi++) {
            int m0 = mt * BM + wr * 64 + mi * 16 + gq;
#pragma unroll
            for (int h = 0; h < 2; h++) {
                int m = m0 + h * 8;
                if (m < count) {
                    float v0 = acc[mi][ni][h * 2 + 0] + bb0;
                    float v1 = acc[mi][ni][h * 2 + 1] + bb1;
                    v0 = 0.5f * v0 * (1.f + erff(v0 * 0.7071067811865476f));
                    v1 = 0.5f * v1 * (1.f + erff(v1 * 0.7071067811865476f));
                    float2 st2 = make_float2(to_tf32(v0), to_tf32(v1));
                    *(float2*)&g_hid[(size_t)(base + m) * FDIM + col] = st2;
                }
            }
        }
    }
}

// ---------------- GEMM2: out[token] += w * (hid @ W2_e + b2_e) ----------------
__global__ __launch_bounds__(256) void gemm2_kernel(const float* __restrict__ b2, float* __restrict__ out) {
    const int e = blockIdx.z;
    const int count = g_counts[e];
    const int mt = blockIdx.y;
    if (mt * BM >= count) return;
    const int nBase = blockIdx.x * BN;
    const int base = g_bases[e];

    __shared__ float sA[2][BM * SA_STRIDE];
    __shared__ float sB[2][BK * SB_STRIDE];
    __shared__ int sTok[BM];
    __shared__ float sWgt[BM];

    const int tid = threadIdx.x;
    if (tid < BM) {
        int m = mt * BM + tid;
        if (m >= count) m = count - 1;
        int tk = g_tokList[e * T_TOK + m];
        sTok[tid] = tk;
        sWgt[tid] = g_wTE[tk * NEXP + e];
    }
    __syncthreads();

    const int chA = tid * 2;
    const int rA = chA >> 2;
    const int ccA = chA & 3;
    int mrowA = mt * BM + rA;
    if (mrowA >= count) mrowA = count - 1;
    const float* gA = g_hid + (size_t)(base + mrowA) * FDIM + ccA * 4;
    uint32_t sAaddr0 = (uint32_t)__cvta_generic_to_shared(&sA[0][rA * SA_STRIDE + ccA * 4]);
    uint32_t sAaddr1 = (uint32_t)__cvta_generic_to_shared(&sA[1][rA * SA_STRIDE + ccA * 4]);

    const int chB = tid * 2;
    const int rB = chB >> 5;
    const int ccB = chB & 31;
    const float* gB = g_w2c + ((size_t)e * FDIM + rB) * HDIM + nBase + ccB * 4;
    uint32_t sBaddr0 = (uint32_t)__cvta_generic_to_shared(&sB[0][rB * SB_STRIDE + ccB * 4]);
    uint32_t sBaddr1 = (uint32_t)__cvta_generic_to_shared(&sB[1][rB * SB_STRIDE + ccB * 4]);

    auto loadTile = [&](int stage, int kt) {
        const float* a0 = gA + kt * BK;
        uint32_t sa = stage ? sAaddr1 : sAaddr0;
        cp16(sa, a0);
        cp16(sa + 16, a0 + 4);
        const float* b0 = gB + (size_t)kt * BK * HDIM;
        uint32_t sb = stage ? sBaddr1 : sBaddr0;
        cp16(sb, b0);
        cp16(sb + 16, b0 + 4);
    };

    float acc[4][4][4];
#pragma unroll
    for (int a = 0; a < 4; a++)
#pragma unroll
        for (int b = 0; b < 4; b++)
#pragma unroll
            for (int c = 0; c < 4; c++) acc[a][b][c] = 0.f;

    const int warp = tid >> 5, lane = tid & 31;
    const int wr = warp >> 2, wc = warp & 3;
    const int gq = lane >> 2, c4 = lane & 3;

    const int KT = FDIM / BK;
    loadTile(0, 0);
    cp_commit();
    for (int kt = 0; kt < KT; kt++) {
        cp_wait0();
        __syncthreads();
        if (kt + 1 < KT) { loadTile((kt + 1) & 1, kt + 1); cp_commit(); }
        const float* pA = sA[kt & 1];
        const float* pB = sB[kt & 1];
#pragma unroll
        for (int ks = 0; ks < 2; ks++) {
            const int k0 = ks * 8;
            uint32_t af[4][4], bf[4][2];
#pragma unroll
            for (int mi = 0; mi < 4; mi++) {
                int r0 = wr * 64 + mi * 16 + gq;
                af[mi][0] = __float_as_uint(pA[r0 * SA_STRIDE + k0 + c4]);
                af[mi][1] = __float_as_uint(pA[(r0 + 8) * SA_STRIDE + k0 + c4]);
                af[mi][2] = __float_as_uint(pA[r0 * SA_STRIDE + k0 + c4 + 4]);
                af[mi][3] = __float_as_uint(pA[(r0 + 8) * SA_STRIDE + k0 + c4 + 4]);
            }
#pragma unroll
            for (int ni = 0; ni < 4; ni++) {
                int cb = wc * 32 + ni * 8 + gq;
                bf[ni][0] = __float_as_uint(pB[(k0 + c4) * SB_STRIDE + cb]);
                bf[ni][1] = __float_as_uint(pB[(k0 + c4 + 4) * SB_STRIDE + cb]);
            }
#pragma unroll
            for (int mi = 0; mi < 4; mi++)
#pragma unroll
                for (int ni = 0; ni < 4; ni++)
                    mma_tf32(acc[mi][ni], af[mi], bf[ni]);
        }
        __syncthreads();
    }

    // epilogue: scale by routing weight, scatter-add into output rows
#pragma unroll
    for (int ni = 0; ni < 4; ni++) {
        int col = nBase + wc * 32 + ni * 8 + 2 * c4;
        float bb0 = b2[e * HDIM + col];
        float bb1 = b2[e * HDIM + col + 1];
#pragma unroll
        for (int mi = 0; mi < 4; mi++) {
            int ml0 = wr * 64 + mi * 16 + gq;
#pragma unroll
            for (int h = 0; h < 2; h++) {
                int ml = ml0 + h * 8;
                int m = mt * BM + ml;
                if (m < count) {
                    int tk = sTok[ml];
                    float w = sWgt[ml];
                    float v0 = w * (acc[mi][ni][h * 2 + 0] + bb0);
                    float v1 = w * (acc[mi][ni][h * 2 + 1] + bb1);
                    atomicAdd(&out[(size_t)tk * HDIM + col], v0);
                    atomicAdd(&out[(size_t)tk * HDIM + col + 1], v1);
                }
            }
        }
    }
}

// ---------------- launch ----------------
extern "C" void kernel_launch(void* const* d_in, const int* in_sizes, int n_in,
                              void* d_out, int out_size) {
    const float* x  = (const float*)d_in[0];
    const float* rw = (const float*)d_in[1];
    const float* w1 = (const float*)d_in[2];
    const float* b1 = (const float*)d_in[3];
    const float* w2 = (const float*)d_in[4];
    const float* b2 = (const float*)d_in[5];
    float* out = (float*)d_out;

    zero_kernel<<<1024, 256>>>((float4*)out, T_TOK * HDIM / 4);
    cvt_x_kernel<<<2048, 256>>>(x);
    cvt_w1_kernel<<<4096, 256>>>(w1);
    cvt_w2_kernel<<<4096, 256>>>(w2);
    router_kernel<<<T_TOK / 8, 256>>>(x, rw);
    compact_kernel<<<NEXP, 256>>>();
    bases_kernel<<<1, 32>>>();
    gemm1_kernel<<<dim3(FDIM / BN, T_TOK / BM, NEXP), 256>>>(b1);
    gemm2_kernel<<<dim3(HDIM / BN, T_TOK / BM, NEXP), 256>>>(b2, out);
}

// round 15
// speedup vs baseline: 1.7729x; 1.7729x over previous
#include <cuda_runtime.h>
#include <cuda_fp16.h>
#include <cstdint>
#include <math.h>

#define T_TOK 8192
#define HDIM 1024
#define FDIM 4096
#define NEXP 8
#define NSLOT (2*T_TOK)

// GEMM tile (legacy mma.m16n8k16.f16, fp32 accum), 2-stage static-smem pipeline
#define BM 128
#define BN 128
#define BK 32
#define RSTRIDE 40   // halfs per smem row (80B: 16B-aligned, 32-distinct-bank fragment reads)

// ---------------- scratch (device globals; no allocation allowed) ----------------
__device__ __half g_xc [(size_t)T_TOK * HDIM];        // fp16-rounded x
__device__ __half g_w1t[(size_t)NEXP * HDIM * FDIM];  // fp16 w1, transposed [E][F][H]
__device__ __half g_w2t[(size_t)NEXP * FDIM * HDIM];  // fp16 w2, transposed [E][H][F]
__device__ __half g_hid[(size_t)NSLOT * FDIM];        // fp16 gelu intermediate
__device__ float g_wTE[T_TOK * NEXP];                 // dense routing weights
__device__ int   g_topk[T_TOK * 2];
__device__ int   g_tokList[NEXP * T_TOK];
__device__ int   g_counts[NEXP];
__device__ int   g_bases[NEXP];

// ---------------- helpers ----------------
__device__ __forceinline__ void cp16(uint32_t s, const void* g) {
    asm volatile("cp.async.cg.shared.global [%0], [%1], 16;\n" :: "r"(s), "l"(g));
}
__device__ __forceinline__ void cp_commit() { asm volatile("cp.async.commit_group;\n" ::: "memory"); }
__device__ __forceinline__ void cp_wait0()  { asm volatile("cp.async.wait_group 0;\n" ::: "memory"); }

__device__ __forceinline__ void mma_f16(float* d, const uint32_t* a, const uint32_t* b) {
    asm volatile(
        "mma.sync.aligned.m16n8k16.row.col.f32.f16.f16.f32 "
        "{%0,%1,%2,%3}, {%4,%5,%6,%7}, {%8,%9}, {%0,%1,%2,%3};\n"
        : "+f"(d[0]), "+f"(d[1]), "+f"(d[2]), "+f"(d[3])
        : "r"(a[0]), "r"(a[1]), "r"(a[2]), "r"(a[3]), "r"(b[0]), "r"(b[1]));
}

// ---------------- small kernels ----------------
__global__ void zero_kernel(float4* out, int n4) {
    int i = blockIdx.x * blockDim.x + threadIdx.x;
    int st = gridDim.x * blockDim.x;
    float4 z = make_float4(0.f, 0.f, 0.f, 0.f);
    for (; i < n4; i += st) out[i] = z;
}

__global__ void cvt_x_kernel(const float* __restrict__ src) {
    int i = blockIdx.x * blockDim.x + threadIdx.x;
    int st = gridDim.x * blockDim.x;
    const float4* s4 = (const float4*)src;
    __half2* d2 = (__half2*)g_xc;
    for (; i < T_TOK * HDIM / 4; i += st) {
        float4 v = s4[i];
        d2[2 * i]     = __floats2half2_rn(v.x, v.y);
        d2[2 * i + 1] = __floats2half2_rn(v.z, v.w);
    }
}

// Transpose + fp16 round: src fp32 [e][R][C] -> device-global dst half [e][C][R].
// WHICH=0: w1 [E][H][F] -> g_w1t [E][F][H];  WHICH=1: w2 [E][F][H] -> g_w2t [E][H][F].
// dst is selected INSIDE the kernel — never pass __device__ symbols from host code.
template<int WHICH>
__global__ void cvt_t_kernel(const float* __restrict__ src) {
    constexpr int R = WHICH ? FDIM : HDIM;
    constexpr int C = WHICH ? HDIM : FDIM;
    __half* __restrict__ dstg = WHICH ? g_w2t : g_w1t;
    __shared__ float tile[32][33];
    int e = blockIdx.z;
    const float* s = src + (size_t)e * R * C;
    __half* d = dstg + (size_t)e * R * C;
    int c0 = blockIdx.x * 32, r0 = blockIdx.y * 32;
    int tx = threadIdx.x, ty = threadIdx.y;  // 32 x 8
#pragma unroll
    for (int j = 0; j < 32; j += 8)
        tile[ty + j][tx] = s[(size_t)(r0 + ty + j) * C + c0 + tx];
    __syncthreads();
#pragma unroll
    for (int j = 0; j < 32; j += 8)
        d[(size_t)(c0 + ty + j) * R + r0 + tx] = __float2half_rn(tile[tx][ty + j]);
}

// Router: warp per token. fp32 logits -> softmax -> stable top-2.
__global__ void router_kernel(const float* __restrict__ x, const float* __restrict__ rw) {
    __shared__ float sw[NEXP * HDIM];
    for (int i = threadIdx.x; i < NEXP * HDIM; i += blockDim.x) sw[i] = rw[i];
    __syncthreads();
    int warp = threadIdx.x >> 5, lane = threadIdx.x & 31;
    int t = blockIdx.x * 8 + warp;
    const float* xr = x + (size_t)t * HDIM;
    float acc[NEXP];
#pragma unroll
    for (int e = 0; e < NEXP; e++) acc[e] = 0.f;
    for (int i = lane; i < HDIM; i += 32) {
        float xv = xr[i];
#pragma unroll
        for (int e = 0; e < NEXP; e++) acc[e] += xv * sw[e * HDIM + i];
    }
#pragma unroll
    for (int off = 16; off > 0; off >>= 1)
#pragma unroll
        for (int e = 0; e < NEXP; e++) acc[e] += __shfl_down_sync(0xffffffffu, acc[e], off);
    if (lane == 0) {
        float mx = acc[0];
#pragma unroll
        for (int e = 1; e < NEXP; e++) mx = fmaxf(mx, acc[e]);
        float p[NEXP]; float s = 0.f;
#pragma unroll
        for (int e = 0; e < NEXP; e++) { p[e] = expf(acc[e] - mx); s += p[e]; }
        int i0 = 0;
#pragma unroll
        for (int e = 1; e < NEXP; e++) if (p[e] > p[i0]) i0 = e;
        int i1 = (i0 == 0) ? 1 : 0;
#pragma unroll
        for (int e = 0; e < NEXP; e++) if (e != i0 && p[e] > p[i1]) i1 = e;
        float inv = 1.f / s;
#pragma unroll
        for (int e = 0; e < NEXP; e++)
            g_wTE[t * NEXP + e] = (e == i0 || e == i1) ? p[e] * inv : 0.f;
        g_topk[t * 2]     = i0;
        g_topk[t * 2 + 1] = i1;
    }
}

// Deterministic compaction: one block per expert, ascending token order.
__global__ void compact_kernel() {
    int e = blockIdx.x;
    __shared__ int wsum[8];
    __shared__ int sBase;
    int tid = threadIdx.x, wid = tid >> 5, lane = tid & 31;
    if (tid == 0) sBase = 0;
    __syncthreads();
    for (int t0 = 0; t0 < T_TOK; t0 += 256) {
        int t = t0 + tid;
        bool sel = (g_topk[t * 2] == e) || (g_topk[t * 2 + 1] == e);
        unsigned bal = __ballot_sync(0xffffffffu, sel);
        int lanePre = __popc(bal & ((1u << lane) - 1u));
        if (lane == 0) wsum[wid] = __popc(bal);
        __syncthreads();
        int wpre = 0;
        for (int w = 0; w < wid; w++) wpre += wsum[w];
        if (sel) g_tokList[e * T_TOK + sBase + wpre + lanePre] = t;
        __syncthreads();
        if (tid == 0) {
            int tt = 0;
            for (int w = 0; w < 8; w++) tt += wsum[w];
            sBase += tt;
        }
        __syncthreads();
    }
    if (tid == 0) g_counts[e] = sBase;
}

__global__ void bases_kernel() {
    if (threadIdx.x == 0 && blockIdx.x == 0) {
        int s = 0;
        for (int e = 0; e < NEXP; e++) { g_bases[e] = s; s += g_counts[e]; }
    }
}

// ---------------- fp16 grouped GEMM (128x128x32, m16n8k16.f16, fp32 accum) ----------------
// IS_G1: hid = gelu(X[gather] @ W1t^T + b1)     (ND=FDIM, KD=HDIM)
// else : out[tok] += w * (hid @ W2t^T + b2)     (ND=HDIM, KD=FDIM)
template<int KT, int ND, int KD, bool IS_G1>
__global__ __launch_bounds__(256) void moe_gemm_fp16(const float* __restrict__ bias_g,
                                                     float* __restrict__ out) {
    const int e = blockIdx.z;
    const int count = g_counts[e];
    const int mt = blockIdx.y;
    if (mt * BM >= count) return;
    const int nBase = blockIdx.x * BN;
    const int base = g_bases[e];
    const int tid = threadIdx.x;

    __shared__ __half sA[2][BM * RSTRIDE];   // 20480 B
    __shared__ __half sB[2][BN * RSTRIDE];   // 20480 B
    __shared__ int sTok[BM];
    __shared__ float sWgt[BM];
    __shared__ float sBias[BN];

    if (tid < BM) {
        int m = mt * BM + tid;
        if (m >= count) m = count - 1;
        int tk = g_tokList[e * T_TOK + m];
        sTok[tid] = tk;
        if (!IS_G1) sWgt[tid] = g_wTE[tk * NEXP + e];
        sBias[tid] = bias_g[e * ND + nBase + tid];
    }
    __syncthreads();

    // gmem row pointers: 2 threads per row, each thread moves 2x16B chunks per stage
    const int rA = tid >> 1;            // 0..127
    const int cHalf = (tid & 1) * 16;   // half offset within the 32-half row
    const __half* aRow;
    if (IS_G1) {
        aRow = g_xc + (size_t)sTok[rA] * KD + cHalf;
    } else {
        int m = mt * BM + rA; if (m >= count) m = count - 1;
        aRow = g_hid + (size_t)(base + m) * KD + cHalf;
    }
    const __half* bRow = (IS_G1 ? g_w1t : g_w2t) + ((size_t)e * ND + nBase + rA) * KD + cHalf;

    const uint32_t saA0 = (uint32_t)__cvta_generic_to_shared(&sA[0][rA * RSTRIDE + cHalf]);
    const uint32_t saA1 = (uint32_t)__cvta_generic_to_shared(&sA[1][rA * RSTRIDE + cHalf]);
    const uint32_t saB0 = (uint32_t)__cvta_generic_to_shared(&sB[0][rA * RSTRIDE + cHalf]);
    const uint32_t saB1 = (uint32_t)__cvta_generic_to_shared(&sB[1][rA * RSTRIDE + cHalf]);

    auto loadStage = [&](int st) {
        uint32_t sa = (st & 1) ? saA1 : saA0;
        uint32_t sb = (st & 1) ? saB1 : saB0;
        const __half* ga = aRow + st * BK;
        const __half* gb = bRow + st * BK;
        cp16(sa,      ga);
        cp16(sa + 16, ga + 8);
        cp16(sb,      gb);
        cp16(sb + 16, gb + 8);
        cp_commit();
    };

    float acc[4][4][4];
#pragma unroll
    for (int a = 0; a < 4; a++)
#pragma unroll
        for (int b = 0; b < 4; b++)
#pragma unroll
            for (int c = 0; c < 4; c++) acc[a][b][c] = 0.f;

    const int warp = tid >> 5, lane = tid & 31;
    const int wr = warp >> 2, wc = warp & 3;       // 2x4 warp grid: 64-row x 32-col warp tiles
    const int g = lane >> 2, t4 = lane & 3;
    const int RS2 = RSTRIDE / 2;                   // half2 per smem row (20)

    loadStage(0);

    for (int kt = 0; kt < KT; kt++) {
        cp_wait0();
        __syncthreads();
        if (kt + 1 < KT) loadStage(kt + 1);

        const __half2* pA = (const __half2*)sA[kt & 1];
        const __half2* pB = (const __half2*)sB[kt & 1];

#pragma unroll
        for (int ks = 0; ks < 2; ks++) {
            const int kh = ks * 8;     // half2 offset of this k16 step
            uint32_t af[4][4], bf[4][2];
#pragma unroll
            for (int mi = 0; mi < 4; mi++) {
                int r0 = wr * 64 + mi * 16 + g;
                af[mi][0] = *(const uint32_t*)&pA[r0 * RS2 + kh + t4];
                af[mi][1] = *(const uint32_t*)&pA[(r0 + 8) * RS2 + kh + t4];
                af[mi][2] = *(const uint32_t*)&pA[r0 * RS2 + kh + 4 + t4];
                af[mi][3] = *(const uint32_t*)&pA[(r0 + 8) * RS2 + kh + 4 + t4];
            }
#pragma unroll
            for (int ni = 0; ni < 4; ni++) {
                int nn = wc * 32 + ni * 8 + g;
                bf[ni][0] = *(const uint32_t*)&pB[nn * RS2 + kh + t4];
                bf[ni][1] = *(const uint32_t*)&pB[nn * RS2 + kh + 4 + t4];
            }
#pragma unroll
            for (int mi = 0; mi < 4; mi++)
#pragma unroll
                for (int ni = 0; ni < 4; ni++)
                    mma_f16(acc[mi][ni], af[mi], bf[ni]);
        }
        __syncthreads();
    }

    // epilogue
#pragma unroll
    for (int ni = 0; ni < 4; ni++) {
        int colL = wc * 32 + ni * 8 + 2 * t4;
        int col = nBase + colL;
        float bb0 = sBias[colL];
        float bb1 = sBias[colL + 1];
#pragma unroll
        for (int mi = 0; mi < 4; mi++) {
            int ml0 = wr * 64 + mi * 16 + g;
#pragma unroll
            for (int h = 0; h < 2; h++) {
                int ml = ml0 + h * 8;
                int m = mt * BM + ml;
                if (m < count) {
                    float v0 = acc[mi][ni][h * 2 + 0] + bb0;
                    float v1 = acc[mi][ni][h * 2 + 1] + bb1;
                    if (IS_G1) {
                        v0 = 0.5f * v0 * (1.f + erff(v0 * 0.7071067811865476f));
                        v1 = 0.5f * v1 * (1.f + erff(v1 * 0.7071067811865476f));
                        *(__half2*)&g_hid[(size_t)(base + m) * FDIM + col] = __floats2half2_rn(v0, v1);
                    } else {
                        int tk = sTok[ml];
                        float w = sWgt[ml];
                        atomicAdd(&out[(size_t)tk * HDIM + col],     w * v0);
                        atomicAdd(&out[(size_t)tk * HDIM + col + 1], w * v1);
                    }
                }
            }
        }
    }
}

// ---------------- launch ----------------
extern "C" void kernel_launch(void* const* d_in, const int* in_sizes, int n_in,
                              void* d_out, int out_size) {
    const float* x  = (const float*)d_in[0];
    const float* rw = (const float*)d_in[1];
    const float* w1 = (const float*)d_in[2];
    const float* b1 = (const float*)d_in[3];
    const float* w2 = (const float*)d_in[4];
    const float* b2 = (const float*)d_in[5];
    float* out = (float*)d_out;

    zero_kernel<<<1024, 256>>>((float4*)out, T_TOK * HDIM / 4);
    cvt_x_kernel<<<2048, 256>>>(x);
    // w1 [E][H][F] -> g_w1t [E][F][H]  (dst bound inside kernel)
    cvt_t_kernel<0><<<dim3(FDIM/32, HDIM/32, NEXP), dim3(32, 8)>>>(w1);
    // w2 [E][F][H] -> g_w2t [E][H][F]  (dst bound inside kernel)
    cvt_t_kernel<1><<<dim3(HDIM/32, FDIM/32, NEXP), dim3(32, 8)>>>(w2);
    router_kernel<<<T_TOK / 8, 256>>>(x, rw);
    compact_kernel<<<NEXP, 256>>>();
    bases_kernel<<<1, 32>>>();
    moe_gemm_fp16<HDIM/BK, FDIM, HDIM, true><<<dim3(FDIM/BN, T_TOK/BM, NEXP), 256>>>(b1, nullptr);
    moe_gemm_fp16<FDIM/BK, HDIM, FDIM, false><<<dim3(HDIM/BN, T_TOK/BM, NEXP), 256>>>(b2, out);
}